// round 9
// baseline (speedup 1.0000x reference)
#include <cuda_runtime.h>
#include <cuda_bf16.h>
#include <cstdint>
#include <cstddef>

#define BATCH   4096
#define TSTEPS  256
#define FDIM    64
#define G4      64      // 4*H
#define HID     16
#define DDIM    64
#define TILE_M  64
#define NROWS_TOT (BATCH * TSTEPS)        // 1048576
#define NTILES    (NROWS_TOT / TILE_M)    // 16384

// scratch: permuted gate pre-activations (+bias) xw[row][h*4 + gate], fp32
__device__ float g_xw[(size_t)NROWS_TOT * G4];

// ---------------- helpers ----------------
__device__ __forceinline__ uint32_t cvt2hi(float a, float b) {
    uint32_t r;
    asm("cvt.rn.bf16x2.f32 %0, %1, %2;" : "=r"(r) : "f"(b), "f"(a));
    return r;
}
__device__ __forceinline__ uint32_t cvt2lo(float a, float b, uint32_t h) {
    float ah = __uint_as_float(h << 16);
    float bh = __uint_as_float(h & 0xffff0000u);
    return cvt2hi(a - ah, b - bh);
}
__device__ __forceinline__ float sigm(float x) {
    float t;
    asm("tanh.approx.f32 %0, %1;" : "=f"(t) : "f"(0.5f * x));
    return fmaf(0.5f, t, 0.5f);
}

// warp-level bf16 MMA, sm_80+ (works on base sm_103 target)
__device__ __forceinline__ void mma16816(float* c, const uint32_t* a,
                                         uint32_t b0, uint32_t b1) {
    asm volatile(
        "mma.sync.aligned.m16n8k16.row.col.f32.bf16.bf16.f32 "
        "{%0,%1,%2,%3}, {%4,%5,%6,%7}, {%8,%9}, {%0,%1,%2,%3};"
        : "+f"(c[0]), "+f"(c[1]), "+f"(c[2]), "+f"(c[3])
        : "r"(a[0]), "r"(a[1]), "r"(a[2]), "r"(a[3]), "r"(b0), "r"(b1));
}

// ================= Kernel 1: xw = x @ W + b  (bf16 hi/lo split, mma.sync) =================
// CTA = 128 threads = 4 warps; warp w computes one m16 tile: rows [16w, 16w+16) of a
// 64-row CTA tile. B columns pre-permuted so output col j == gate index h*4+gate.
// All A data (one full 64-float row pair per thread) loaded up-front (MLP=16).
__global__ void __launch_bounds__(128)
gemm_xw_kernel(const float* __restrict__ xg, const float* __restrict__ Wg,
               const float* __restrict__ bg)
{
    // Bs[kp*68 + j] = (hi, lo) bf16x2 pair of { Bp[2kp][j], Bp[2kp+1][j] },
    // Bp[k][j] = W[k][(j%4)*16 + j/4].  stride 68 -> <=2-way LDS conflicts.
    __shared__ uint2 Bs[32 * 68];
    __shared__ float biasp[64];

    const int tid  = threadIdx.x;
    const int lane = tid & 31;
    const int w    = tid >> 5;
    const int g    = lane >> 2;   // groupID 0..7
    const int kq   = lane & 3;    // threadID_in_group 0..3

    // ---- build permuted B (+bias) in smem ----
    for (int idx = tid; idx < 2048; idx += 128) {
        int kp = idx >> 6;            // 0..31 (k = 2*kp)
        int j  = idx & 63;            // permuted output column
        int c  = (j & 3) * 16 + (j >> 2);   // original W column
        float w0 = Wg[(2 * kp)     * G4 + c];
        float w1 = Wg[(2 * kp + 1) * G4 + c];
        uint32_t hp = cvt2hi(w0, w1);
        Bs[kp * 68 + j] = make_uint2(hp, cvt2lo(w0, w1, hp));
    }
    if (tid < 64) biasp[tid] = bg[(tid & 3) * 16 + (tid >> 2)];
    __syncthreads();

    const size_t rowbase = (size_t)blockIdx.x * TILE_M + (size_t)w * 16;
    const float* base0 = xg + (rowbase + (size_t)g) * FDIM + 2 * kq;

    // ---- batched A loads: rows g and g+8, all 64 k values (16 x LDG.64) ----
    float2 va[2][4][2];
    #pragma unroll
    for (int kk = 0; kk < 4; kk++) {
        #pragma unroll
        for (int hf = 0; hf < 2; hf++) {
            va[0][kk][hf] = *(const float2*)(base0 + 16 * kk + 8 * hf);
            va[1][kk][hf] = *(const float2*)(base0 + 8 * FDIM + 16 * kk + 8 * hf);
        }
    }

    // ---- convert to bf16 hi/lo fragments ----
    uint32_t ah[4][4], al[4][4];
    #pragma unroll
    for (int kk = 0; kk < 4; kk++) {
        ah[kk][0] = cvt2hi(va[0][kk][0].x, va[0][kk][0].y);
        ah[kk][1] = cvt2hi(va[1][kk][0].x, va[1][kk][0].y);
        ah[kk][2] = cvt2hi(va[0][kk][1].x, va[0][kk][1].y);
        ah[kk][3] = cvt2hi(va[1][kk][1].x, va[1][kk][1].y);
        al[kk][0] = cvt2lo(va[0][kk][0].x, va[0][kk][0].y, ah[kk][0]);
        al[kk][1] = cvt2lo(va[1][kk][0].x, va[1][kk][0].y, ah[kk][1]);
        al[kk][2] = cvt2lo(va[0][kk][1].x, va[0][kk][1].y, ah[kk][2]);
        al[kk][3] = cvt2lo(va[1][kk][1].x, va[1][kk][1].y, ah[kk][3]);
    }

    float acc[8][4];
    #pragma unroll
    for (int n = 0; n < 8; n++)
        #pragma unroll
        for (int r = 0; r < 4; r++) acc[n][r] = 0.0f;

    // ---- MMAs: hi*hi + lo*hi + hi*lo ----
    #pragma unroll
    for (int kk = 0; kk < 4; kk++) {
        #pragma unroll
        for (int n = 0; n < 8; n++) {
            int j = 8 * n + g;
            uint2 b0 = Bs[(kq + 8 * kk)     * 68 + j];   // k-pair k0,   (hi,lo)
            uint2 b1 = Bs[(kq + 4 + 8 * kk) * 68 + j];   // k-pair k0+8, (hi,lo)
            mma16816(acc[n], ah[kk], b0.x, b1.x);   // hi*hi
            mma16816(acc[n], al[kk], b0.x, b1.x);   // lo*hi
            mma16816(acc[n], ah[kk], b0.y, b1.y);   // hi*lo
        }
    }

    // ---- epilogue: add permuted bias, contiguous float2 stores ----
    {
        size_t r0 = rowbase + (size_t)g;
        #pragma unroll
        for (int n = 0; n < 8; n++) {
            int j0 = 8 * n + 2 * kq;
            float2 bi = *(const float2*)&biasp[j0];
            *(float2*)(g_xw + r0 * G4 + j0) =
                make_float2(acc[n][0] + bi.x, acc[n][1] + bi.y);
            *(float2*)(g_xw + (r0 + 8) * G4 + j0) =
                make_float2(acc[n][2] + bi.x, acc[n][3] + bi.y);
        }
    }
}

// ================= Kernel 2: recurrence + dense + normalize =================
// 32 threads (one warp) per batch row. Lane (k, half): k = lane&15 owns hidden unit k
// (h[k], c[k] computed redundantly on both halves); half = lane>>4 selects the j-range
// of the 16-term recurrent dot product (j = 8*half .. 8*half+7). Partial z combined
// with one shfl_xor(16). Sigmoid via tanh.approx.
__global__ void __launch_bounds__(128)
lstm_rec_kernel(const float* __restrict__ Ug,
                const float* __restrict__ Wdg, const float* __restrict__ bdg,
                float* __restrict__ outg)
{
    const int lane = threadIdx.x & 31;
    const int k    = lane & 15;
    const int half = lane >> 4;
    const int jb   = half << 3;                      // 0 or 8
    const int row  = blockIdx.x * 4 + (threadIdx.x >> 5);

    // U slice for this lane's j-range
    float u0[8], u1[8], u2[8], u3[8];
    #pragma unroll
    for (int j = 0; j < 8; j++) {
        const float* uj = Ug + (jb + j) * G4;
        u0[j] = uj[k];
        u1[j] = uj[k + 16];
        u2[j] = uj[k + 32];
        u3[j] = uj[k + 48];
    }

    float h = 0.0f, c = 0.0f;
    const float4* xp = (const float4*)(g_xw + (size_t)row * TSTEPS * G4) + k;
    float4 cur = make_float4(0.f, 0.f, 0.f, 0.f);
    if (half == 0) cur = xp[0];

    for (int t = 0; t < TSTEPS; t++) {
        float4 nxt = cur;
        if (half == 0 && t + 1 < TSTEPS) nxt = xp[(t + 1) * 16];

        // broadcast h[jb..jb+7] (lanes 0..15 hold h[0..15])
        float hj[8];
        #pragma unroll
        for (int j = 0; j < 8; j++) hj[j] = __shfl_sync(0xffffffffu, h, jb + j, 32);

        float z0 = cur.x, z1 = cur.y, z2 = cur.z, z3 = cur.w;  // half1: zeros
        #pragma unroll
        for (int j = 0; j < 8; j++) {
            z0 = fmaf(hj[j], u0[j], z0);
            z1 = fmaf(hj[j], u1[j], z1);
            z2 = fmaf(hj[j], u2[j], z2);
            z3 = fmaf(hj[j], u3[j], z3);
        }
        z0 += __shfl_xor_sync(0xffffffffu, z0, 16, 32);
        z1 += __shfl_xor_sync(0xffffffffu, z1, 16, 32);
        z2 += __shfl_xor_sync(0xffffffffu, z2, 16, 32);
        z3 += __shfl_xor_sync(0xffffffffu, z3, 16, 32);

        float ig = sigm(z0);
        float fg = sigm(z1);
        float gg = fmaxf(z2, 0.0f);
        float og = sigm(z3);
        c = fmaf(fg, c, ig * gg);
        h = og * fmaxf(c, 0.0f);
        cur = nxt;
    }

    // dense: out = sigmoid(h @ Wd + bd); lane computes cols c0 = 4k+2*half, c0+1
    float hj[16];
    #pragma unroll
    for (int j = 0; j < 16; j++) hj[j] = __shfl_sync(0xffffffffu, h, j, 32);

    const int c0 = 4 * k + 2 * half;
    float a0 = 0.f, a1 = 0.f;
    #pragma unroll
    for (int j = 0; j < 16; j++) {
        float2 w2 = *(const float2*)(Wdg + j * DDIM + c0);
        a0 = fmaf(hj[j], w2.x, a0);
        a1 = fmaf(hj[j], w2.y, a1);
    }
    float2 bd2 = *(const float2*)(bdg + c0);
    a0 = sigm(a0 + bd2.x);
    a1 = sigm(a1 + bd2.y);

    float s = a0 + a1;
    #pragma unroll
    for (int off = 16; off; off >>= 1) s += __shfl_xor_sync(0xffffffffu, s, off, 32);
    float inv = __fdividef(1.0f, s);

    *(float2*)(outg + (size_t)row * DDIM + c0) = make_float2(a0 * inv, a1 * inv);
}

// ================= launch =================
extern "C" void kernel_launch(void* const* d_in, const int* in_sizes, int n_in,
                              void* d_out, int out_size)
{
    const float* x  = (const float*)d_in[0];
    const float* W  = (const float*)d_in[1];
    const float* U  = (const float*)d_in[2];
    const float* b  = (const float*)d_in[3];
    const float* Wd = (const float*)d_in[4];
    const float* bd = (const float*)d_in[5];
    float* out = (float*)d_out;

    gemm_xw_kernel<<<NTILES, 128>>>(x, W, b);
    lstm_rec_kernel<<<BATCH / 4, 128>>>(U, Wd, bd, out);
}

// round 10
// speedup vs baseline: 1.2541x; 1.2541x over previous
#include <cuda_runtime.h>
#include <cuda_bf16.h>
#include <cstdint>
#include <cstddef>

#define BATCH   4096
#define TSTEPS  256
#define FDIM    64
#define G4      64      // 4*H
#define HID     16
#define DDIM    64
#define TILE_M  128
#define NROWS_TOT (BATCH * TSTEPS)        // 1048576
#define NTILES    (NROWS_TOT / TILE_M)    // 8192

// scratch: permuted gate pre-activations (+bias) xw[row][h*4 + gate], fp32
__device__ float g_xw[(size_t)NROWS_TOT * G4];
// prepacked B: g_Bp[kp*64 + j] = (hi,lo) bf16x2 of {Bp[2kp][j], Bp[2kp+1][j]},
// Bp[k][j] = W[k][(j%4)*16 + j/4]
__device__ uint2 g_Bp[2048];
__device__ float g_biasp[64];

// ---------------- helpers ----------------
__device__ __forceinline__ uint32_t cvt2hi(float a, float b) {
    uint32_t r;
    asm("cvt.rn.bf16x2.f32 %0, %1, %2;" : "=r"(r) : "f"(b), "f"(a));
    return r;
}
__device__ __forceinline__ uint32_t cvt2lo(float a, float b, uint32_t h) {
    float ah = __uint_as_float(h << 16);
    float bh = __uint_as_float(h & 0xffff0000u);
    return cvt2hi(a - ah, b - bh);
}
__device__ __forceinline__ float sigm(float x) {
    float t;
    asm("tanh.approx.f32 %0, %1;" : "=f"(t) : "f"(0.5f * x));
    return fmaf(0.5f, t, 0.5f);
}

// warp-level bf16 MMA, sm_80+ (works on base sm_103 target)
__device__ __forceinline__ void mma16816(float* c, const uint32_t* a,
                                         uint32_t b0, uint32_t b1) {
    asm volatile(
        "mma.sync.aligned.m16n8k16.row.col.f32.bf16.bf16.f32 "
        "{%0,%1,%2,%3}, {%4,%5,%6,%7}, {%8,%9}, {%0,%1,%2,%3};"
        : "+f"(c[0]), "+f"(c[1]), "+f"(c[2]), "+f"(c[3])
        : "r"(a[0]), "r"(a[1]), "r"(a[2]), "r"(a[3]), "r"(b0), "r"(b1));
}

// ================= Kernel 0: pack B + bias (runs once per launch, 1 CTA) =================
__global__ void pack_kernel(const float* __restrict__ Wg, const float* __restrict__ bg)
{
    int tid = threadIdx.x;
    for (int i = tid; i < 2048; i += 256) {
        int kp = i >> 6;                   // 0..31 (k = 2*kp)
        int j  = i & 63;                   // permuted output column
        int c  = (j & 3) * 16 + (j >> 2);  // original W column
        float w0 = Wg[(2 * kp)     * G4 + c];
        float w1 = Wg[(2 * kp + 1) * G4 + c];
        uint32_t hp = cvt2hi(w0, w1);
        g_Bp[i] = make_uint2(hp, cvt2lo(w0, w1, hp));
    }
    if (tid < 64) g_biasp[tid] = bg[(tid & 3) * 16 + (tid >> 2)];
}

// ================= Kernel 1: xw = x @ W + b  (bf16 hi/lo split, mma.sync) =================
// CTA = 128 threads = 4 warps; warp w covers rows [32w, 32w+32) of a 128-row tile
// as two m16 tiles. A loads batched (MLP=16) and overlapped with B smem copy / MMAs.
struct AFrag { uint32_t ah[4][4], al[4][4]; };

__device__ __forceinline__ void load_A(float2 va[2][4][2], const float* base) {
    #pragma unroll
    for (int kk = 0; kk < 4; kk++)
        #pragma unroll
        for (int hf = 0; hf < 2; hf++) {
            va[0][kk][hf] = *(const float2*)(base + 16 * kk + 8 * hf);
            va[1][kk][hf] = *(const float2*)(base + 8 * FDIM + 16 * kk + 8 * hf);
        }
}
__device__ __forceinline__ void cvt_A(AFrag& f, const float2 va[2][4][2]) {
    #pragma unroll
    for (int kk = 0; kk < 4; kk++) {
        f.ah[kk][0] = cvt2hi(va[0][kk][0].x, va[0][kk][0].y);
        f.ah[kk][1] = cvt2hi(va[1][kk][0].x, va[1][kk][0].y);
        f.ah[kk][2] = cvt2hi(va[0][kk][1].x, va[0][kk][1].y);
        f.ah[kk][3] = cvt2hi(va[1][kk][1].x, va[1][kk][1].y);
        f.al[kk][0] = cvt2lo(va[0][kk][0].x, va[0][kk][0].y, f.ah[kk][0]);
        f.al[kk][1] = cvt2lo(va[1][kk][0].x, va[1][kk][0].y, f.ah[kk][1]);
        f.al[kk][2] = cvt2lo(va[0][kk][1].x, va[0][kk][1].y, f.ah[kk][2]);
        f.al[kk][3] = cvt2lo(va[1][kk][1].x, va[1][kk][1].y, f.ah[kk][3]);
    }
}

__global__ void __launch_bounds__(128, 4)
gemm_xw_kernel(const float* __restrict__ xg)
{
    __shared__ uint2 Bs[32 * 68];     // stride 68 -> <=2-way LDS conflicts
    __shared__ float biasp_s[64];

    const int tid  = threadIdx.x;
    const int lane = tid & 31;
    const int w    = tid >> 5;
    const int g    = lane >> 2;   // groupID 0..7
    const int kq   = lane & 3;    // threadID_in_group 0..3

    const size_t rowbase = (size_t)blockIdx.x * TILE_M + (size_t)w * 32;
    const float* base0 = xg + (rowbase + (size_t)g) * FDIM + 2 * kq;

    // ---- issue mt0 A loads first (16 LDG.64, in flight during B copy) ----
    float2 va[2][4][2];
    load_A(va, base0);

    // ---- copy prepacked B + bias into smem (L2-hit) ----
    for (int i = tid; i < 2048; i += 128)
        Bs[(i >> 6) * 68 + (i & 63)] = g_Bp[i];
    if (tid < 64) biasp_s[tid] = g_biasp[tid];
    __syncthreads();

    AFrag f;
    cvt_A(f, va);
    load_A(va, base0 + 16 * FDIM);    // mt1 loads in flight during mt0 MMAs

    #pragma unroll
    for (int mt = 0; mt < 2; mt++) {
        if (mt == 1) cvt_A(f, va);

        float acc[8][4];
        #pragma unroll
        for (int n = 0; n < 8; n++)
            #pragma unroll
            for (int r = 0; r < 4; r++) acc[n][r] = 0.0f;

        #pragma unroll
        for (int kk = 0; kk < 4; kk++) {
            #pragma unroll
            for (int n = 0; n < 8; n++) {
                int j = 8 * n + g;
                uint2 b0 = Bs[(kq + 8 * kk)     * 68 + j];   // k-pair k0   (hi,lo)
                uint2 b1 = Bs[(kq + 4 + 8 * kk) * 68 + j];   // k-pair k0+8 (hi,lo)
                mma16816(acc[n], f.ah[kk], b0.x, b1.x);   // hi*hi
                mma16816(acc[n], f.al[kk], b0.x, b1.x);   // lo*hi
                mma16816(acc[n], f.ah[kk], b0.y, b1.y);   // hi*lo
            }
        }

        // ---- epilogue: add permuted bias, contiguous float2 stores ----
        size_t r0 = rowbase + (size_t)(mt * 16 + g);
        #pragma unroll
        for (int n = 0; n < 8; n++) {
            int j0 = 8 * n + 2 * kq;
            float2 bi = *(const float2*)&biasp_s[j0];
            *(float2*)(g_xw + r0 * G4 + j0) =
                make_float2(acc[n][0] + bi.x, acc[n][1] + bi.y);
            *(float2*)(g_xw + (r0 + 8) * G4 + j0) =
                make_float2(acc[n][2] + bi.x, acc[n][3] + bi.y);
        }
    }
}

// ================= Kernel 2: recurrence + dense + normalize =================
// 16 threads per batch row (2 rows per warp). Thread k owns h[k], c[k] and gate
// columns 4k..4k+3 of the permuted xw. U in registers; h via width-16 shuffles
// (16 shfl serve both rows of the warp). Recurrent dot split into two 8-deep
// FMA chains. Sigmoid via tanh.approx. Bias already folded into xw.
__global__ void __launch_bounds__(128)
lstm_rec_kernel(const float* __restrict__ Ug,
                const float* __restrict__ Wdg, const float* __restrict__ bdg,
                float* __restrict__ outg)
{
    const int k   = threadIdx.x & 15;
    const int row = blockIdx.x * 8 + (threadIdx.x >> 4);

    float u0[HID], u1[HID], u2[HID], u3[HID];
    #pragma unroll
    for (int j = 0; j < HID; j++) {
        const float* uj = Ug + j * G4;
        u0[j] = uj[k];
        u1[j] = uj[k + 16];
        u2[j] = uj[k + 32];
        u3[j] = uj[k + 48];
    }

    float h = 0.0f, c = 0.0f;
    const float4* xp = (const float4*)(g_xw + (size_t)row * TSTEPS * G4) + k;
    float4 cur = xp[0];

    for (int t = 0; t < TSTEPS; t++) {
        float4 nxt = cur;
        if (t + 1 < TSTEPS) nxt = xp[(t + 1) * 16];   // prefetch next step

        float hj[HID];
        #pragma unroll
        for (int j = 0; j < HID; j++) hj[j] = __shfl_sync(0xffffffffu, h, j, 16);

        // two independent 8-deep FMA chains per gate
        float z0a = cur.x, z1a = cur.y, z2a = cur.z, z3a = cur.w;
        float z0b = 0.f, z1b = 0.f, z2b = 0.f, z3b = 0.f;
        #pragma unroll
        for (int j = 0; j < 8; j++) {
            z0a = fmaf(hj[j], u0[j], z0a);
            z1a = fmaf(hj[j], u1[j], z1a);
            z2a = fmaf(hj[j], u2[j], z2a);
            z3a = fmaf(hj[j], u3[j], z3a);
            z0b = fmaf(hj[j + 8], u0[j + 8], z0b);
            z1b = fmaf(hj[j + 8], u1[j + 8], z1b);
            z2b = fmaf(hj[j + 8], u2[j + 8], z2b);
            z3b = fmaf(hj[j + 8], u3[j + 8], z3b);
        }
        float ig = sigm(z0a + z0b);
        float fg = sigm(z1a + z1b);
        float gg = fmaxf(z2a + z2b, 0.0f);
        float og = sigm(z3a + z3b);
        c = fmaf(fg, c, ig * gg);
        h = og * fmaxf(c, 0.0f);
        cur = nxt;
    }

    // dense: out = sigmoid(h @ Wd + bd), thread k computes cols 4k..4k+3
    float hj[HID];
    #pragma unroll
    for (int j = 0; j < HID; j++) hj[j] = __shfl_sync(0xffffffffu, h, j, 16);

    float a0 = 0.f, a1 = 0.f, a2 = 0.f, a3 = 0.f;
    #pragma unroll
    for (int j = 0; j < HID; j++) {
        float4 w4 = *(const float4*)(Wdg + j * DDIM + 4 * k);
        a0 = fmaf(hj[j], w4.x, a0);
        a1 = fmaf(hj[j], w4.y, a1);
        a2 = fmaf(hj[j], w4.z, a2);
        a3 = fmaf(hj[j], w4.w, a3);
    }
    float4 bd4 = *(const float4*)(bdg + 4 * k);
    a0 = sigm(a0 + bd4.x);
    a1 = sigm(a1 + bd4.y);
    a2 = sigm(a2 + bd4.z);
    a3 = sigm(a3 + bd4.w);

    float s = a0 + a1 + a2 + a3;
    #pragma unroll
    for (int off = 8; off; off >>= 1) s += __shfl_xor_sync(0xffffffffu, s, off, 16);
    float inv = __fdividef(1.0f, s);

    float4 o4 = make_float4(a0 * inv, a1 * inv, a2 * inv, a3 * inv);
    *((float4*)(outg + (size_t)row * DDIM + 4 * k)) = o4;
}

// ================= launch =================
extern "C" void kernel_launch(void* const* d_in, const int* in_sizes, int n_in,
                              void* d_out, int out_size)
{
    const float* x  = (const float*)d_in[0];
    const float* W  = (const float*)d_in[1];
    const float* U  = (const float*)d_in[2];
    const float* b  = (const float*)d_in[3];
    const float* Wd = (const float*)d_in[4];
    const float* bd = (const float*)d_in[5];
    float* out = (float*)d_out;

    pack_kernel<<<1, 256>>>(W, b);
    gemm_xw_kernel<<<NTILES, 128>>>(x);
    lstm_rec_kernel<<<BATCH / 8, 128>>>(U, Wd, bd, out);
}

// round 11
// speedup vs baseline: 2.0464x; 1.6318x over previous
#include <cuda_runtime.h>
#include <cuda_bf16.h>
#include <cstdint>
#include <cstddef>

#define BATCH   4096
#define TSTEPS  256
#define FDIM    64
#define G4      64      // 4*H
#define HID     16
#define DDIM    64
#define CH      8                    // timesteps per chunk
#define NCH     (TSTEPS / CH)        // 32 chunks

// ---------------- helpers ----------------
__device__ __forceinline__ uint32_t cvt2hi(float a, float b) {
    uint32_t r;
    asm("cvt.rn.bf16x2.f32 %0, %1, %2;" : "=r"(r) : "f"(b), "f"(a));
    return r;
}
__device__ __forceinline__ uint32_t cvt2lo(float a, float b, uint32_t h) {
    float ah = __uint_as_float(h << 16);
    float bh = __uint_as_float(h & 0xffff0000u);
    return cvt2hi(a - ah, b - bh);
}
__device__ __forceinline__ float sigm(float x) {
    float t;
    asm("tanh.approx.f32 %0, %1;" : "=f"(t) : "f"(0.5f * x));
    return fmaf(0.5f, t, 0.5f);
}
// warp-level bf16 MMA, sm_80+ (works on base sm_103 target)
__device__ __forceinline__ void mma16816(float* c, const uint32_t* a,
                                         uint32_t b0, uint32_t b1) {
    asm volatile(
        "mma.sync.aligned.m16n8k16.row.col.f32.bf16.bf16.f32 "
        "{%0,%1,%2,%3}, {%4,%5,%6,%7}, {%8,%9}, {%0,%1,%2,%3};"
        : "+f"(c[0]), "+f"(c[1]), "+f"(c[2]), "+f"(c[3])
        : "r"(a[0]), "r"(a[1]), "r"(a[2]), "r"(a[3]), "r"(b0), "r"(b1));
}

// ================= Fused kernel: GEMM chunk -> smem -> recurrence, per warp =================
// CTA = 128 threads = 4 warps. Warp w owns batch rows rA = blk*8+2w, rB = rA+1.
// Per chunk (8 timesteps): m16n64k64 GEMM (m rows 0-7 = rowA t0..t0+7, 8-15 = rowB),
// bf16 hi/lo split vs gate-permuted W in smem; stage gate tile in per-warp smem;
// then 8 recurrence steps (lanes 0-15 = rowA, 16-31 = rowB). Bias folded at read.
__global__ void __launch_bounds__(128, 3)
fused_lstm_kernel(const float* __restrict__ xg, const float* __restrict__ Wg,
                  const float* __restrict__ Ug, const float* __restrict__ bg,
                  const float* __restrict__ Wdg, const float* __restrict__ bdg,
                  float* __restrict__ outg)
{
    // Bs[kp*68 + j] = (hi,lo) bf16x2 of {Bp[2kp][j], Bp[2kp+1][j]},
    // Bp[k][j] = W[k][(j%4)*16 + j/4]   (gate-permuted columns)
    __shared__ uint2 Bs[32 * 68];                       // 17408 B
    __shared__ __align__(16) float xw_s[4][2][CH][68];  // 17408 B, stride 68 (16B-mult)

    const int tid  = threadIdx.x;
    const int lane = tid & 31;
    const int w    = tid >> 5;
    const int g    = lane >> 2;    // MMA groupID 0..7
    const int kq   = lane & 3;     // MMA thread-in-group 0..3
    const int k    = lane & 15;    // hidden unit owned in recurrence
    const int half = lane >> 4;    // 0 = rowA, 1 = rowB

    // ---- build permuted B in smem (once per CTA) ----
    for (int i = tid; i < 2048; i += 128) {
        int kp = i >> 6;                   // 0..31 (k = 2*kp)
        int j  = i & 63;                   // permuted output column
        int c  = (j & 3) * 16 + (j >> 2);  // original W column
        float w0 = Wg[(2 * kp)     * G4 + c];
        float w1 = Wg[(2 * kp + 1) * G4 + c];
        uint32_t hp = cvt2hi(w0, w1);
        Bs[kp * 68 + j] = make_uint2(hp, cvt2lo(w0, w1, hp));
    }
    __syncthreads();

    // ---- recurrence constants in registers ----
    float u0[HID], u1[HID], u2[HID], u3[HID];
    #pragma unroll
    for (int j = 0; j < HID; j++) {
        const float* uj = Ug + j * G4;
        u0[j] = uj[k];
        u1[j] = uj[k + 16];
        u2[j] = uj[k + 32];
        u3[j] = uj[k + 48];
    }
    // permuted col 4k+gate <-> b[gate*16 + k]
    const float4 bias4 = make_float4(bg[k], bg[k + 16], bg[k + 32], bg[k + 48]);

    const int rA = blockIdx.x * 8 + 2 * w;
    const float* xA = xg + (size_t)rA * TSTEPS * FDIM + 2 * kq;
    const float* xB = xA + TSTEPS * FDIM;

    float* wbufA = &xw_s[w][0][0][0];
    const float* mybuf = &xw_s[w][half][0][0] + 4 * k;

    float h = 0.0f, cc = 0.0f;

    for (int ch = 0; ch < NCH; ch++) {
        const int t0 = ch * CH;

        // ---- A loads: rowA & rowB, t = t0+g, all 64 k (16 x LDG.64, batched) ----
        float2 va[4][2], vb[4][2];
        {
            const float* pA = xA + (size_t)(t0 + g) * FDIM;
            const float* pB = xB + (size_t)(t0 + g) * FDIM;
            #pragma unroll
            for (int kk = 0; kk < 4; kk++) {
                #pragma unroll
                for (int hf = 0; hf < 2; hf++) {
                    va[kk][hf] = *(const float2*)(pA + 16 * kk + 8 * hf);
                    vb[kk][hf] = *(const float2*)(pB + 16 * kk + 8 * hf);
                }
            }
        }

        // ---- convert to bf16 hi/lo fragments (m rows: g=rowA, g+8=rowB) ----
        uint32_t fh[4][4], fl[4][4];
        #pragma unroll
        for (int kk = 0; kk < 4; kk++) {
            fh[kk][0] = cvt2hi(va[kk][0].x, va[kk][0].y);
            fh[kk][1] = cvt2hi(vb[kk][0].x, vb[kk][0].y);
            fh[kk][2] = cvt2hi(va[kk][1].x, va[kk][1].y);
            fh[kk][3] = cvt2hi(vb[kk][1].x, vb[kk][1].y);
            fl[kk][0] = cvt2lo(va[kk][0].x, va[kk][0].y, fh[kk][0]);
            fl[kk][1] = cvt2lo(vb[kk][0].x, vb[kk][0].y, fh[kk][1]);
            fl[kk][2] = cvt2lo(va[kk][1].x, va[kk][1].y, fh[kk][2]);
            fl[kk][3] = cvt2lo(vb[kk][1].x, vb[kk][1].y, fh[kk][3]);
        }

        // ---- MMAs: hi*hi + lo*hi + hi*lo ----
        float acc[8][4];
        #pragma unroll
        for (int n = 0; n < 8; n++)
            #pragma unroll
            for (int r = 0; r < 4; r++) acc[n][r] = 0.0f;

        #pragma unroll
        for (int kk = 0; kk < 4; kk++) {
            #pragma unroll
            for (int n = 0; n < 8; n++) {
                int j = 8 * n + g;
                uint2 b0 = Bs[(kq + 8 * kk)     * 68 + j];
                uint2 b1 = Bs[(kq + 4 + 8 * kk) * 68 + j];
                mma16816(acc[n], fh[kk], b0.x, b1.x);   // hi*hi
                mma16816(acc[n], fl[kk], b0.x, b1.x);   // lo*hi
                mma16816(acc[n], fh[kk], b0.y, b1.y);   // hi*lo
            }
        }

        // ---- stage gate tile in smem (prev chunk's reads already done) ----
        __syncwarp();
        {
            float* rowAb = wbufA + g * 68;          // xw_s[w][0][g][*]
            float* rowBb = rowAb + CH * 68;         // xw_s[w][1][g][*]
            #pragma unroll
            for (int n = 0; n < 8; n++) {
                int j0 = 8 * n + 2 * kq;
                *(float2*)(rowAb + j0) = make_float2(acc[n][0], acc[n][1]);
                *(float2*)(rowBb + j0) = make_float2(acc[n][2], acc[n][3]);
            }
        }
        __syncwarp();

        // ---- recurrence: CH steps; lanes 0-15 rowA, 16-31 rowB ----
        #pragma unroll
        for (int tt = 0; tt < CH; tt++) {
            float4 cur = *(const float4*)(mybuf + tt * 68);

            float hj[HID];
            #pragma unroll
            for (int j = 0; j < HID; j++) hj[j] = __shfl_sync(0xffffffffu, h, j, 16);

            float z0a = cur.x + bias4.x, z1a = cur.y + bias4.y;
            float z2a = cur.z + bias4.z, z3a = cur.w + bias4.w;
            float z0b = 0.f, z1b = 0.f, z2b = 0.f, z3b = 0.f;
            #pragma unroll
            for (int j = 0; j < 8; j++) {
                z0a = fmaf(hj[j], u0[j], z0a);
                z1a = fmaf(hj[j], u1[j], z1a);
                z2a = fmaf(hj[j], u2[j], z2a);
                z3a = fmaf(hj[j], u3[j], z3a);
                z0b = fmaf(hj[j + 8], u0[j + 8], z0b);
                z1b = fmaf(hj[j + 8], u1[j + 8], z1b);
                z2b = fmaf(hj[j + 8], u2[j + 8], z2b);
                z3b = fmaf(hj[j + 8], u3[j + 8], z3b);
            }
            float ig = sigm(z0a + z0b);
            float fg = sigm(z1a + z1b);
            float gg = fmaxf(z2a + z2b, 0.0f);
            float og = sigm(z3a + z3b);
            cc = fmaf(fg, cc, ig * gg);
            h  = og * fmaxf(cc, 0.0f);
        }
    }

    // ---- dense: out = sigmoid(h @ Wd + bd); thread k -> cols 4k..4k+3 ----
    float hj[HID];
    #pragma unroll
    for (int j = 0; j < HID; j++) hj[j] = __shfl_sync(0xffffffffu, h, j, 16);

    float a0 = 0.f, a1 = 0.f, a2 = 0.f, a3 = 0.f;
    #pragma unroll
    for (int j = 0; j < HID; j++) {
        float4 w4 = *(const float4*)(Wdg + j * DDIM + 4 * k);
        a0 = fmaf(hj[j], w4.x, a0);
        a1 = fmaf(hj[j], w4.y, a1);
        a2 = fmaf(hj[j], w4.z, a2);
        a3 = fmaf(hj[j], w4.w, a3);
    }
    float4 bd4 = *(const float4*)(bdg + 4 * k);
    a0 = sigm(a0 + bd4.x);
    a1 = sigm(a1 + bd4.y);
    a2 = sigm(a2 + bd4.z);
    a3 = sigm(a3 + bd4.w);

    float s = a0 + a1 + a2 + a3;
    #pragma unroll
    for (int off = 8; off; off >>= 1) s += __shfl_xor_sync(0xffffffffu, s, off, 16);
    float inv = __fdividef(1.0f, s);

    float4 o4 = make_float4(a0 * inv, a1 * inv, a2 * inv, a3 * inv);
    *((float4*)(outg + (size_t)(rA + half) * DDIM + 4 * k)) = o4;
}

// ================= launch =================
extern "C" void kernel_launch(void* const* d_in, const int* in_sizes, int n_in,
                              void* d_out, int out_size)
{
    const float* x  = (const float*)d_in[0];
    const float* W  = (const float*)d_in[1];
    const float* U  = (const float*)d_in[2];
    const float* b  = (const float*)d_in[3];
    const float* Wd = (const float*)d_in[4];
    const float* bd = (const float*)d_in[5];
    float* out = (float*)d_out;

    fused_lstm_kernel<<<BATCH / 8, 128>>>(x, W, U, b, Wd, bd, out);
}

// round 12
// speedup vs baseline: 2.3000x; 1.1239x over previous
#include <cuda_runtime.h>
#include <cuda_bf16.h>
#include <cstdint>
#include <cstddef>

#define BATCH   4096
#define TSTEPS  256
#define FDIM    64
#define G4      64      // 4*H
#define HID     16
#define DDIM    64
#define CH      8                    // timesteps per chunk
#define NCH     (TSTEPS / CH)        // 32 chunks

// ---------------- helpers ----------------
__device__ __forceinline__ uint32_t cvt2hi(float a, float b) {
    uint32_t r;
    asm("cvt.rn.bf16x2.f32 %0, %1, %2;" : "=r"(r) : "f"(b), "f"(a));
    return r;
}
__device__ __forceinline__ uint32_t cvt2lo(float a, float b, uint32_t h) {
    float ah = __uint_as_float(h << 16);
    float bh = __uint_as_float(h & 0xffff0000u);
    return cvt2hi(a - ah, b - bh);
}
__device__ __forceinline__ float sigm(float x) {
    float t;
    asm("tanh.approx.f32 %0, %1;" : "=f"(t) : "f"(0.5f * x));
    return fmaf(0.5f, t, 0.5f);
}
// warp-level bf16 MMA, sm_80+ (works on base sm_103 target)
__device__ __forceinline__ void mma16816(float* c, const uint32_t* a,
                                         uint32_t b0, uint32_t b1) {
    asm volatile(
        "mma.sync.aligned.m16n8k16.row.col.f32.bf16.bf16.f32 "
        "{%0,%1,%2,%3}, {%4,%5,%6,%7}, {%8,%9}, {%0,%1,%2,%3};"
        : "+f"(c[0]), "+f"(c[1]), "+f"(c[2]), "+f"(c[3])
        : "r"(a[0]), "r"(a[1]), "r"(a[2]), "r"(a[3]), "r"(b0), "r"(b1));
}

// ================= Fused kernel: GEMM chunk -> smem -> recurrence, per warp =================
// CTA = 128 threads = 4 warps. Warp w owns batch rows rA = blk*8+2w, rB = rA+1.
// Per chunk (8 timesteps): m16n64k64 GEMM (m rows 0-7 = rowA t0..t0+7, 8-15 = rowB),
// bf16 hi/lo split vs gate-permuted W in smem; stage gate tile (+bias) in per-warp smem;
// then 8 recurrence steps (lanes 0-15 = rowA, 16-31 = rowB).
__global__ void __launch_bounds__(128, 4)
fused_lstm_kernel(const float* __restrict__ xg, const float* __restrict__ Wg,
                  const float* __restrict__ Ug, const float* __restrict__ bg,
                  const float* __restrict__ Wdg, const float* __restrict__ bdg,
                  float* __restrict__ outg)
{
    // Bs[kp*68 + j] = (hi,lo) bf16x2 of {Bp[2kp][j], Bp[2kp+1][j]},
    // Bp[k][j] = W[k][(j%4)*16 + j/4]   (gate-permuted columns)
    __shared__ uint2 Bs[32 * 68];                       // 17408 B
    __shared__ __align__(16) float xw_s[4][2][CH][68];  // 17408 B, stride 68 (16B-mult)
    __shared__ float biasp_s[64];                       // permuted bias

    const int tid  = threadIdx.x;
    const int lane = tid & 31;
    const int w    = tid >> 5;
    const int g    = lane >> 2;    // MMA groupID 0..7
    const int kq   = lane & 3;     // MMA thread-in-group 0..3
    const int k    = lane & 15;    // hidden unit owned in recurrence
    const int half = lane >> 4;    // 0 = rowA, 1 = rowB

    // ---- build permuted B + bias in smem (once per CTA) ----
    for (int i = tid; i < 2048; i += 128) {
        int kp = i >> 6;                   // 0..31 (k = 2*kp)
        int j  = i & 63;                   // permuted output column
        int c  = (j & 3) * 16 + (j >> 2);  // original W column
        float w0 = Wg[(2 * kp)     * G4 + c];
        float w1 = Wg[(2 * kp + 1) * G4 + c];
        uint32_t hp = cvt2hi(w0, w1);
        Bs[kp * 68 + j] = make_uint2(hp, cvt2lo(w0, w1, hp));
    }
    if (tid < 64) biasp_s[tid] = bg[(tid & 3) * 16 + (tid >> 2)];
    __syncthreads();

    // ---- recurrence constants in registers ----
    float u0[HID], u1[HID], u2[HID], u3[HID];
    #pragma unroll
    for (int j = 0; j < HID; j++) {
        const float* uj = Ug + j * G4;
        u0[j] = uj[k];
        u1[j] = uj[k + 16];
        u2[j] = uj[k + 32];
        u3[j] = uj[k + 48];
    }

    const int rA = blockIdx.x * 8 + 2 * w;
    const float* xA = xg + (size_t)rA * TSTEPS * FDIM + 2 * kq;
    const float* xB = xA + TSTEPS * FDIM;

    float* wbufA = &xw_s[w][0][0][0];
    const float* mybuf = &xw_s[w][half][0][0] + 4 * k;

    float h = 0.0f, cc = 0.0f;

    for (int ch = 0; ch < NCH; ch++) {
        const int t0 = ch * CH;

        // ---- A loads: rowA & rowB, t = t0+g, all 64 k (16 x LDG.64, batched) ----
        float2 va[4][2], vb[4][2];
        {
            const float* pA = xA + (size_t)(t0 + g) * FDIM;
            const float* pB = xB + (size_t)(t0 + g) * FDIM;
            #pragma unroll
            for (int kk = 0; kk < 4; kk++) {
                #pragma unroll
                for (int hf = 0; hf < 2; hf++) {
                    va[kk][hf] = *(const float2*)(pA + 16 * kk + 8 * hf);
                    vb[kk][hf] = *(const float2*)(pB + 16 * kk + 8 * hf);
                }
            }
        }

        float acc[8][4];
        #pragma unroll
        for (int n = 0; n < 8; n++)
            #pragma unroll
            for (int r = 0; r < 4; r++) acc[n][r] = 0.0f;

        // ---- per-kk: convert fragments (short live range), then MMAs ----
        #pragma unroll
        for (int kk = 0; kk < 4; kk++) {
            uint32_t fh[4], fl[4];
            fh[0] = cvt2hi(va[kk][0].x, va[kk][0].y);
            fh[1] = cvt2hi(vb[kk][0].x, vb[kk][0].y);
            fh[2] = cvt2hi(va[kk][1].x, va[kk][1].y);
            fh[3] = cvt2hi(vb[kk][1].x, vb[kk][1].y);
            fl[0] = cvt2lo(va[kk][0].x, va[kk][0].y, fh[0]);
            fl[1] = cvt2lo(vb[kk][0].x, vb[kk][0].y, fh[1]);
            fl[2] = cvt2lo(va[kk][1].x, va[kk][1].y, fh[2]);
            fl[3] = cvt2lo(vb[kk][1].x, vb[kk][1].y, fh[3]);

            #pragma unroll
            for (int n = 0; n < 8; n++) {
                int j = 8 * n + g;
                uint2 b0 = Bs[(kq + 8 * kk)     * 68 + j];
                uint2 b1 = Bs[(kq + 4 + 8 * kk) * 68 + j];
                mma16816(acc[n], fh, b0.x, b1.x);   // hi*hi
                mma16816(acc[n], fl, b0.x, b1.x);   // lo*hi
                mma16816(acc[n], fh, b0.y, b1.y);   // hi*lo
            }
        }

        // ---- stage gate tile (+bias) in smem ----
        __syncwarp();
        {
            float* rowAb = wbufA + g * 68;          // xw_s[w][0][g][*]
            float* rowBb = rowAb + CH * 68;         // xw_s[w][1][g][*]
            #pragma unroll
            for (int n = 0; n < 8; n++) {
                int j0 = 8 * n + 2 * kq;
                float2 bi = *(const float2*)&biasp_s[j0];
                *(float2*)(rowAb + j0) = make_float2(acc[n][0] + bi.x, acc[n][1] + bi.y);
                *(float2*)(rowBb + j0) = make_float2(acc[n][2] + bi.x, acc[n][3] + bi.y);
            }
        }
        __syncwarp();

        // ---- recurrence: CH steps; lanes 0-15 rowA, 16-31 rowB ----
        #pragma unroll
        for (int tt = 0; tt < CH; tt++) {
            float4 cur = *(const float4*)(mybuf + tt * 68);

            float hj[HID];
            #pragma unroll
            for (int j = 0; j < HID; j++) hj[j] = __shfl_sync(0xffffffffu, h, j, 16);

            float z0a = cur.x, z1a = cur.y, z2a = cur.z, z3a = cur.w;
            float z0b = 0.f, z1b = 0.f, z2b = 0.f, z3b = 0.f;
            #pragma unroll
            for (int j = 0; j < 8; j++) {
                z0a = fmaf(hj[j], u0[j], z0a);
                z1a = fmaf(hj[j], u1[j], z1a);
                z2a = fmaf(hj[j], u2[j], z2a);
                z3a = fmaf(hj[j], u3[j], z3a);
                z0b = fmaf(hj[j + 8], u0[j + 8], z0b);
                z1b = fmaf(hj[j + 8], u1[j + 8], z1b);
                z2b = fmaf(hj[j + 8], u2[j + 8], z2b);
                z3b = fmaf(hj[j + 8], u3[j + 8], z3b);
            }
            float ig = sigm(z0a + z0b);
            float fg = sigm(z1a + z1b);
            float gg = fmaxf(z2a + z2b, 0.0f);
            float og = sigm(z3a + z3b);
            cc = fmaf(fg, cc, ig * gg);
            h  = og * fmaxf(cc, 0.0f);
        }
    }

    // ---- dense: out = sigmoid(h @ Wd + bd); thread k -> cols 4k..4k+3 ----
    float hj[HID];
    #pragma unroll
    for (int j = 0; j < HID; j++) hj[j] = __shfl_sync(0xffffffffu, h, j, 16);

    float a0 = 0.f, a1 = 0.f, a2 = 0.f, a3 = 0.f;
    #pragma unroll
    for (int j = 0; j < HID; j++) {
        float4 w4 = *(const float4*)(Wdg + j * DDIM + 4 * k);
        a0 = fmaf(hj[j], w4.x, a0);
        a1 = fmaf(hj[j], w4.y, a1);
        a2 = fmaf(hj[j], w4.z, a2);
        a3 = fmaf(hj[j], w4.w, a3);
    }
    float4 bd4 = *(const float4*)(bdg + 4 * k);
    a0 = sigm(a0 + bd4.x);
    a1 = sigm(a1 + bd4.y);
    a2 = sigm(a2 + bd4.z);
    a3 = sigm(a3 + bd4.w);

    float s = a0 + a1 + a2 + a3;
    #pragma unroll
    for (int off = 8; off; off >>= 1) s += __shfl_xor_sync(0xffffffffu, s, off, 16);
    float inv = __fdividef(1.0f, s);

    float4 o4 = make_float4(a0 * inv, a1 * inv, a2 * inv, a3 * inv);
    *((float4*)(outg + (size_t)(rA + half) * DDIM + 4 * k)) = o4;
}

// ================= launch =================
extern "C" void kernel_launch(void* const* d_in, const int* in_sizes, int n_in,
                              void* d_out, int out_size)
{
    const float* x  = (const float*)d_in[0];
    const float* W  = (const float*)d_in[1];
    const float* U  = (const float*)d_in[2];
    const float* b  = (const float*)d_in[3];
    const float* Wd = (const float*)d_in[4];
    const float* bd = (const float*)d_in[5];
    float* out = (float*)d_out;

    fused_lstm_kernel<<<BATCH / 8, 128>>>(x, W, U, b, Wd, bd, out);
}